// round 7
// baseline (speedup 1.0000x reference)
#include <cuda_runtime.h>
#include <cuda_bf16.h>
#include <cuda_fp16.h>
#include <float.h>

#define N_NODES 50000
#define N_EDGES 800000
#define IN_CH   128
#define HEADS   4
#define OUT_CH  32
#define HC      128
#define TOT_E   (N_EDGES + N_NODES)
#define NBLK    ((N_NODES + 255) / 256)   // 196 scan blocks

// ---------------- scratch ---------------------------------------------------
__device__ __half g_hh[N_NODES * HC];      // 12.8 MB fp16 h
__device__ float g_asrc[N_NODES * HEADS];
__device__ float g_adst[N_NODES * HEADS];
__device__ int   g_deg[N_NODES];
__device__ int   g_off[N_NODES + 1];
__device__ int   g_cur[N_NODES];
__device__ int   g_csr[TOT_E];
__device__ int   g_bsum[NBLK];
__device__ int   g_bpre[NBLK];
__device__ int   g_is64;

// ---------------- static-init stream/events (pre-baseline, pre-warmed) ------
__global__ void k_noop() {}

struct StreamHolder {
    cudaStream_t s;
    cudaEvent_t  eFork, eJoin;
    StreamHolder() {
        cudaStreamCreate(&s);
        cudaEventCreateWithFlags(&eFork, cudaEventDisableTiming);
        cudaEventCreateWithFlags(&eJoin, cudaEventDisableTiming);
        k_noop<<<1, 32, 0, s>>>();
        k_noop<<<1, 32>>>();
        cudaStreamSynchronize(s);
        cudaStreamSynchronize(0);
    }
};
static StreamHolder g_sh;

// ---------------- init + dtype detect ---------------------------------------
__global__ void k_init(const int* __restrict__ ei32) {
    int i = blockIdx.x * blockDim.x + threadIdx.x;
    if (i < N_NODES) g_deg[i] = 1;           // self loop
    if (i == 0) {
        int nz = 0;
        for (int j = 0; j < 64; ++j) nz |= ei32[2 * j + 1];
        g_is64 = (nz == 0) ? 1 : 0;
    }
}

__device__ __forceinline__ int load_idx(const void* ei, long long pos) {
    if (g_is64) return (int)((const long long*)ei)[pos];
    return ((const int*)ei)[pos];
}

// ---------------- CSR build -------------------------------------------------
__global__ void k_hist(const void* __restrict__ ei) {
    int e = blockIdx.x * blockDim.x + threadIdx.x;
    if (e < N_EDGES) {
        int d = load_idx(ei, (long long)N_EDGES + e);
        if ((unsigned)d < N_NODES) atomicAdd(&g_deg[d], 1);
    }
}

__global__ __launch_bounds__(256) void k_bsum() {
    __shared__ int wsum[8];
    int b = blockIdx.x, t = threadIdx.x;
    int idx = b * 256 + t;
    int v = (idx < N_NODES) ? g_deg[idx] : 0;
#pragma unroll
    for (int o = 16; o; o >>= 1) v += __shfl_xor_sync(~0u, v, o);
    if ((t & 31) == 0) wsum[t >> 5] = v;
    __syncthreads();
    if (t < 8) {
        int s = wsum[t];
#pragma unroll
        for (int o = 4; o; o >>= 1) s += __shfl_xor_sync(0xFFu, s, o);
        if (t == 0) g_bsum[b] = s;
    }
}

__global__ __launch_bounds__(256) void k_bscan() {
    __shared__ int wsum[8];
    int t = threadIdx.x, lane = t & 31, wid = t >> 5;
    int v = (t < NBLK) ? g_bsum[t] : 0;
    int x = v;
#pragma unroll
    for (int o = 1; o < 32; o <<= 1) {
        int y = __shfl_up_sync(~0u, x, o);
        if (lane >= o) x += y;
    }
    if (lane == 31) wsum[wid] = x;
    __syncthreads();
    if (wid == 0) {
        int s = (lane < 8) ? wsum[lane] : 0;
#pragma unroll
        for (int o = 1; o < 8; o <<= 1) {
            int y = __shfl_up_sync(~0u, s, o);
            if (lane >= o) s += y;
        }
        if (lane < 8) wsum[lane] = s;
    }
    __syncthreads();
    int incl = x + (wid ? wsum[wid - 1] : 0);
    if (t < NBLK) g_bpre[t] = incl - v;
    if (t == 255) g_off[N_NODES] = incl;
}

__global__ __launch_bounds__(256) void k_offsets() {
    __shared__ int wsum[8];
    int b = blockIdx.x, t = threadIdx.x, lane = t & 31, wid = t >> 5;
    int idx = b * 256 + t;
    int v = (idx < N_NODES) ? g_deg[idx] : 0;
    int x = v;
#pragma unroll
    for (int o = 1; o < 32; o <<= 1) {
        int y = __shfl_up_sync(~0u, x, o);
        if (lane >= o) x += y;
    }
    if (lane == 31) wsum[wid] = x;
    __syncthreads();
    if (wid == 0) {
        int s = (lane < 8) ? wsum[lane] : 0;
#pragma unroll
        for (int o = 1; o < 8; o <<= 1) {
            int y = __shfl_up_sync(~0u, s, o);
            if (lane >= o) s += y;
        }
        if (lane < 8) wsum[lane] = s;
    }
    __syncthreads();
    int excl = x - v + (wid ? wsum[wid - 1] : 0) + g_bpre[b];
    if (idx < N_NODES) {
        g_off[idx] = excl;
        g_csr[excl] = idx;     // self loop first
        g_cur[idx] = excl + 1;
    }
}

__global__ void k_scatter(const void* __restrict__ ei) {
    int e = blockIdx.x * blockDim.x + threadIdx.x;
    if (e < N_EDGES) {
        int s = load_idx(ei, e);
        int d = load_idx(ei, (long long)N_EDGES + e);
        if ((unsigned)d < N_NODES && (unsigned)s < N_NODES) {
            int p = atomicAdd(&g_cur[d], 1);
            g_csr[p] = s;
        }
    }
}

// ---------------- GEMM h = x@W + fused attention logits ---------------------
__global__ __launch_bounds__(256) void k_gemm(const float* __restrict__ x,
                                              const float* __restrict__ W,
                                              const float* __restrict__ att_src,
                                              const float* __restrict__ att_dst) {
    __shared__ float4 Ws[32 * 32];   // [k][c4]  16 KB
    __shared__ float4 Xs[64 * 8];    // [m][k4]   8 KB
    int tid = threadIdx.x;
    int tx = tid & 31;       // lane: 4 channels each
    int ty = tid >> 5;       // warp: 8 rows each
    int m0 = blockIdx.x * 64;

    float4 acc[8];
#pragma unroll
    for (int i = 0; i < 8; ++i) acc[i] = make_float4(0.f, 0.f, 0.f, 0.f);

    for (int kb = 0; kb < 4; ++kb) {
        const float4* Wg = (const float4*)(W + kb * 32 * HC);
#pragma unroll
        for (int j = 0; j < 4; ++j) {
            int f = tid + j * 256;
            Ws[f] = Wg[f];
        }
#pragma unroll
        for (int j = 0; j < 2; ++j) {
            int f = tid + j * 256;
            int m = f >> 3, k4 = f & 7;
            int gm = m0 + m;
            if (gm >= N_NODES) gm = N_NODES - 1;
            Xs[f] = ((const float4*)(x + (size_t)gm * IN_CH + kb * 32))[k4];
        }
        __syncthreads();
#pragma unroll
        for (int k4 = 0; k4 < 8; ++k4) {
            float4 w0 = Ws[(k4 * 4 + 0) * 32 + tx];
            float4 w1 = Ws[(k4 * 4 + 1) * 32 + tx];
            float4 w2 = Ws[(k4 * 4 + 2) * 32 + tx];
            float4 w3 = Ws[(k4 * 4 + 3) * 32 + tx];
#pragma unroll
            for (int i = 0; i < 8; ++i) {
                float4 xv = Xs[(ty * 8 + i) * 8 + k4];
                acc[i].x += xv.x * w0.x; acc[i].y += xv.x * w0.y;
                acc[i].z += xv.x * w0.z; acc[i].w += xv.x * w0.w;
                acc[i].x += xv.y * w1.x; acc[i].y += xv.y * w1.y;
                acc[i].z += xv.y * w1.z; acc[i].w += xv.y * w1.w;
                acc[i].x += xv.z * w2.x; acc[i].y += xv.z * w2.y;
                acc[i].z += xv.z * w2.z; acc[i].w += xv.z * w2.w;
                acc[i].x += xv.w * w3.x; acc[i].y += xv.w * w3.y;
                acc[i].z += xv.w * w3.z; acc[i].w += xv.w * w3.w;
            }
        }
        __syncthreads();
    }

    float4 s4 = ((const float4*)att_src)[tx];
    float4 d4 = ((const float4*)att_dst)[tx];
    int head = tx >> 3;
#pragma unroll
    for (int i = 0; i < 8; ++i) {
        int m = m0 + ty * 8 + i;
        float ps = acc[i].x * s4.x + acc[i].y * s4.y + acc[i].z * s4.z + acc[i].w * s4.w;
        float pd = acc[i].x * d4.x + acc[i].y * d4.y + acc[i].z * d4.z + acc[i].w * d4.w;
#pragma unroll
        for (int o = 4; o; o >>= 1) {
            ps += __shfl_xor_sync(0xFFFFFFFFu, ps, o);
            pd += __shfl_xor_sync(0xFFFFFFFFu, pd, o);
        }
        if (m < N_NODES) {
            __half2 h01 = __floats2half2_rn(acc[i].x, acc[i].y);
            __half2 h23 = __floats2half2_rn(acc[i].z, acc[i].w);
            uint2 pack;
            pack.x = *(unsigned int*)&h01;
            pack.y = *(unsigned int*)&h23;
            ((uint2*)(g_hh + (size_t)m * HC))[tx] = pack;
            if ((tx & 7) == 0) {
                g_asrc[m * HEADS + head] = ps;
                g_adst[m * HEADS + head] = pd;
            }
        }
    }
}

// ---------------- aggregation: slim per-lane-head loop + fp16 gather --------
__global__ __launch_bounds__(256) void k_agg(const float* __restrict__ bias,
                                             float* __restrict__ out) {
    int w = (blockIdx.x * blockDim.x + threadIdx.x) >> 5;
    int lane = threadIdx.x & 31;
    if (w >= N_NODES) return;
    int s0 = g_off[w], s1 = g_off[w + 1];
    int head = lane >> 3;
    float adm = g_adst[w * HEADS + head];   // this lane's head only

    float4 acc = make_float4(0.f, 0.f, 0.f, 0.f);
    float den = 0.f;

    // pipeline: src index + scalar logit one edge ahead
    int s = g_csr[s0];
    float asv = __ldg(&g_asrc[s * HEADS + head]);
    for (int i = s0; i < s1; ++i) {
        int snext = (i + 1 < s1) ? g_csr[i + 1] : s;
        float asn = __ldg(&g_asrc[snext * HEADS + head]);
        float e = asv + adm;
        e = (e >= 0.f) ? e : 0.2f * e;
        float ph = __expf(e);
        den += ph;
        uint2 hv2 = ((const uint2*)(g_hh + (size_t)s * HC))[lane];
        float2 f01 = __half22float2(*(__half2*)&hv2.x);
        float2 f23 = __half22float2(*(__half2*)&hv2.y);
        acc.x += ph * f01.x; acc.y += ph * f01.y;
        acc.z += ph * f23.x; acc.w += ph * f23.y;
        s = snext; asv = asn;
    }
    float inv = 1.f / (den + 1e-16f);
    float4 b = ((const float4*)bias)[lane];
    float4 o4;
    o4.x = fmaxf(acc.x * inv + b.x, 0.f);
    o4.y = fmaxf(acc.y * inv + b.y, 0.f);
    o4.z = fmaxf(acc.z * inv + b.z, 0.f);
    o4.w = fmaxf(acc.w * inv + b.w, 0.f);
    ((float4*)(out + (size_t)w * HC))[lane] = o4;
}

// ---------------- launch ----------------------------------------------------
extern "C" void kernel_launch(void* const* d_in, const int* in_sizes, int n_in,
                              void* d_out, int out_size) {
    const float* x       = (const float*)d_in[0];
    const void*  ei      = d_in[1];
    const float* W       = (const float*)d_in[2];
    const float* att_src = (const float*)d_in[3];
    const float* att_dst = (const float*)d_in[4];
    const float* bias    = (const float*)d_in[5];
    float*       out     = (float*)d_out;

    (void)in_sizes; (void)n_in; (void)out_size;

    const int TB = 256;
    cudaStream_t s2 = g_sh.s;

    cudaEventRecord(g_sh.eFork, 0);
    cudaStreamWaitEvent(s2, g_sh.eFork, 0);

    k_init<<<(N_NODES + TB - 1) / TB, TB, 0, s2>>>((const int*)ei);
    k_hist<<<(N_EDGES + TB - 1) / TB, TB, 0, s2>>>(ei);
    k_bsum<<<NBLK, 256, 0, s2>>>();
    k_bscan<<<1, 256, 0, s2>>>();
    k_offsets<<<NBLK, 256, 0, s2>>>();
    k_scatter<<<(N_EDGES + TB - 1) / TB, TB, 0, s2>>>(ei);
    cudaEventRecord(g_sh.eJoin, s2);

    k_gemm<<<(N_NODES + 63) / 64, 256>>>(x, W, att_src, att_dst);

    cudaStreamWaitEvent(0, g_sh.eJoin, 0);
    k_agg<<<(N_NODES * 32 + TB - 1) / TB, TB>>>(bias, out);
}

// round 8
// speedup vs baseline: 1.1001x; 1.1001x over previous
#include <cuda_runtime.h>
#include <cuda_bf16.h>
#include <float.h>

#define N_NODES 50000
#define N_EDGES 800000
#define IN_CH   128
#define HEADS   4
#define OUT_CH  32
#define HC      128
#define TOT_E   (N_EDGES + N_NODES)
#define NBLK    ((N_NODES + 255) / 256)   // 196 scan blocks

// ---------------- scratch ---------------------------------------------------
__device__ float g_h[N_NODES * HC];        // 25.6 MB
__device__ float g_asrc[N_NODES * HEADS];
__device__ float g_adst[N_NODES * HEADS];
__device__ int   g_deg[N_NODES];
__device__ int   g_off[N_NODES + 1];
__device__ int   g_cur[N_NODES];
__device__ int   g_csr[TOT_E];
__device__ int   g_bsum[NBLK];
__device__ int   g_bpre[NBLK];
__device__ int   g_is64;

// ---------------- static-init stream/events (pre-baseline, pre-warmed) ------
__global__ void k_noop() {}

struct StreamHolder {
    cudaStream_t s;
    cudaEvent_t  eFork, eJoin;
    StreamHolder() {
        cudaStreamCreate(&s);
        cudaEventCreateWithFlags(&eFork, cudaEventDisableTiming);
        cudaEventCreateWithFlags(&eJoin, cudaEventDisableTiming);
        k_noop<<<1, 32, 0, s>>>();
        k_noop<<<1, 32>>>();
        cudaStreamSynchronize(s);
        cudaStreamSynchronize(0);
    }
};
static StreamHolder g_sh;

// ---------------- init + dtype detect ---------------------------------------
__global__ void k_init(const int* __restrict__ ei32) {
    int i = blockIdx.x * blockDim.x + threadIdx.x;
    if (i < N_NODES) g_deg[i] = 1;           // self loop
    if (i == 0) {
        int nz = 0;
        for (int j = 0; j < 64; ++j) nz |= ei32[2 * j + 1];
        g_is64 = (nz == 0) ? 1 : 0;
    }
}

__device__ __forceinline__ int load_idx(const void* ei, long long pos) {
    if (g_is64) return (int)((const long long*)ei)[pos];
    return ((const int*)ei)[pos];
}

// ---------------- CSR build (4 edges per thread) -----------------------------
__global__ void k_hist(const void* __restrict__ ei) {
    int e0 = (blockIdx.x * blockDim.x + threadIdx.x) * 4;
    if (e0 >= N_EDGES) return;
#pragma unroll
    for (int j = 0; j < 4; ++j) {
        int e = e0 + j;
        if (e < N_EDGES) {
            int d = load_idx(ei, (long long)N_EDGES + e);
            if ((unsigned)d < N_NODES) atomicAdd(&g_deg[d], 1);
        }
    }
}

__global__ __launch_bounds__(256) void k_bsum() {
    __shared__ int wsum[8];
    int b = blockIdx.x, t = threadIdx.x;
    int idx = b * 256 + t;
    int v = (idx < N_NODES) ? g_deg[idx] : 0;
#pragma unroll
    for (int o = 16; o; o >>= 1) v += __shfl_xor_sync(~0u, v, o);
    if ((t & 31) == 0) wsum[t >> 5] = v;
    __syncthreads();
    if (t < 8) {
        int s = wsum[t];
#pragma unroll
        for (int o = 4; o; o >>= 1) s += __shfl_xor_sync(0xFFu, s, o);
        if (t == 0) g_bsum[b] = s;
    }
}

__global__ __launch_bounds__(256) void k_bscan() {
    __shared__ int wsum[8];
    int t = threadIdx.x, lane = t & 31, wid = t >> 5;
    int v = (t < NBLK) ? g_bsum[t] : 0;
    int x = v;
#pragma unroll
    for (int o = 1; o < 32; o <<= 1) {
        int y = __shfl_up_sync(~0u, x, o);
        if (lane >= o) x += y;
    }
    if (lane == 31) wsum[wid] = x;
    __syncthreads();
    if (wid == 0) {
        int s = (lane < 8) ? wsum[lane] : 0;
#pragma unroll
        for (int o = 1; o < 8; o <<= 1) {
            int y = __shfl_up_sync(~0u, s, o);
            if (lane >= o) s += y;
        }
        if (lane < 8) wsum[lane] = s;
    }
    __syncthreads();
    int incl = x + (wid ? wsum[wid - 1] : 0);
    if (t < NBLK) g_bpre[t] = incl - v;
    if (t == 255) g_off[N_NODES] = incl;
}

__global__ __launch_bounds__(256) void k_offsets() {
    __shared__ int wsum[8];
    int b = blockIdx.x, t = threadIdx.x, lane = t & 31, wid = t >> 5;
    int idx = b * 256 + t;
    int v = (idx < N_NODES) ? g_deg[idx] : 0;
    int x = v;
#pragma unroll
    for (int o = 1; o < 32; o <<= 1) {
        int y = __shfl_up_sync(~0u, x, o);
        if (lane >= o) x += y;
    }
    if (lane == 31) wsum[wid] = x;
    __syncthreads();
    if (wid == 0) {
        int s = (lane < 8) ? wsum[lane] : 0;
#pragma unroll
        for (int o = 1; o < 8; o <<= 1) {
            int y = __shfl_up_sync(~0u, s, o);
            if (lane >= o) s += y;
        }
        if (lane < 8) wsum[lane] = s;
    }
    __syncthreads();
    int excl = x - v + (wid ? wsum[wid - 1] : 0) + g_bpre[b];
    if (idx < N_NODES) {
        g_off[idx] = excl;
        g_csr[excl] = idx;     // self loop first
        g_cur[idx] = excl + 1;
    }
}

__global__ void k_scatter(const void* __restrict__ ei) {
    int e0 = (blockIdx.x * blockDim.x + threadIdx.x) * 4;
    if (e0 >= N_EDGES) return;
#pragma unroll
    for (int j = 0; j < 4; ++j) {
        int e = e0 + j;
        if (e < N_EDGES) {
            int s = load_idx(ei, e);
            int d = load_idx(ei, (long long)N_EDGES + e);
            if ((unsigned)d < N_NODES && (unsigned)s < N_NODES) {
                int p = atomicAdd(&g_cur[d], 1);
                g_csr[p] = s;
            }
        }
    }
}

// ---------------- tf32 tensor-core GEMM h = x@W + fused att logits ----------
__device__ __forceinline__ unsigned f2tf32(float f) {
    unsigned r;
    asm("cvt.rna.tf32.f32 %0, %1;" : "=r"(r) : "f"(f));
    return r;
}

// Xs: [row][k] with XOR swizzle on k (bits 2-4 ^= row&7) -> conflict-free frag LDS
__device__ __forceinline__ int xs_idx(int row, int k) {
    return row * 32 + (k ^ ((row & 7) << 2));
}

__global__ __launch_bounds__(256) void k_gemm(const float* __restrict__ x,
                                              const float* __restrict__ W,
                                              const float* __restrict__ att_src,
                                              const float* __restrict__ att_dst) {
    __shared__ unsigned Xs[128 * 32];      // 16 KB, swizzled tf32
    __shared__ uint2    Wsf[4 * 128 * 4];  // 16 KB: [ks][n][kk] -> (B[k][n], B[k+4][n])
    int tid  = threadIdx.x;
    int wid  = tid >> 5, lane = tid & 31;
    int g    = lane >> 2, tq = lane & 3;
    int m0   = blockIdx.x * 128;

    float c[16][4];
#pragma unroll
    for (int nt = 0; nt < 16; ++nt) {
        c[nt][0] = 0.f; c[nt][1] = 0.f; c[nt][2] = 0.f; c[nt][3] = 0.f;
    }

    for (int kc = 0; kc < 128; kc += 32) {
        // stage X chunk: 128 rows x 32 k
#pragma unroll
        for (int j = 0; j < 4; ++j) {
            int f = tid + j * 256;
            int row = f >> 3, k4 = (f & 7) * 4;
            int gm = m0 + row;
            if (gm >= N_NODES) gm = N_NODES - 1;
            float4 v = *(const float4*)(x + (size_t)gm * IN_CH + kc + k4);
            Xs[xs_idx(row, k4 + 0)] = f2tf32(v.x);
            Xs[xs_idx(row, k4 + 1)] = f2tf32(v.y);
            Xs[xs_idx(row, k4 + 2)] = f2tf32(v.z);
            Xs[xs_idx(row, k4 + 3)] = f2tf32(v.w);
        }
        // stage W chunk paired for B frags
#pragma unroll
        for (int j = 0; j < 8; ++j) {
            int f = tid + j * 256;            // 0..2047
            int n = f & 127, t = f >> 7;      // t: 0..15
            int ks = t >> 2, kk = t & 3;
            int k = kc + ks * 8 + kk;
            uint2 p;
            p.x = f2tf32(W[k * HC + n]);
            p.y = f2tf32(W[(k + 4) * HC + n]);
            Wsf[ks * 512 + n * 4 + kk] = p;
        }
        __syncthreads();

#pragma unroll
        for (int ks = 0; ks < 4; ++ks) {
            int kb = ks * 8;
            int rA = wid * 16 + g, rB = rA + 8;
            unsigned a0 = Xs[xs_idx(rA, kb + tq)];
            unsigned a1 = Xs[xs_idx(rB, kb + tq)];
            unsigned a2 = Xs[xs_idx(rA, kb + tq + 4)];
            unsigned a3 = Xs[xs_idx(rB, kb + tq + 4)];
#pragma unroll
            for (int nt = 0; nt < 16; ++nt) {
                uint2 b = Wsf[ks * 512 + (nt * 8 + g) * 4 + tq];
                asm volatile(
                    "mma.sync.aligned.m16n8k8.row.col.f32.tf32.tf32.f32 "
                    "{%0,%1,%2,%3}, {%4,%5,%6,%7}, {%8,%9}, {%0,%1,%2,%3};"
                    : "+f"(c[nt][0]), "+f"(c[nt][1]), "+f"(c[nt][2]), "+f"(c[nt][3])
                    : "r"(a0), "r"(a1), "r"(a2), "r"(a3), "r"(b.x), "r"(b.y));
            }
        }
        __syncthreads();
    }

    // epilogue: rows mA (c0,c1) and mB (c2,c3); fused per-head att dots
    int mA = m0 + wid * 16 + g;
    int mB = mA + 8;
    float keep_sA = 0.f, keep_dA = 0.f, keep_sB = 0.f, keep_dB = 0.f;
#pragma unroll
    for (int head = 0; head < 4; ++head) {
        float sA = 0.f, dA = 0.f, sB = 0.f, dB = 0.f;
#pragma unroll
        for (int q = 0; q < 4; ++q) {
            int nt = head * 4 + q;
            int col = nt * 8 + 2 * tq;
            float as0 = att_src[col], as1 = att_src[col + 1];
            float ad0 = att_dst[col], ad1 = att_dst[col + 1];
            sA += c[nt][0] * as0 + c[nt][1] * as1;
            dA += c[nt][0] * ad0 + c[nt][1] * ad1;
            sB += c[nt][2] * as0 + c[nt][3] * as1;
            dB += c[nt][2] * ad0 + c[nt][3] * ad1;
        }
        sA += __shfl_xor_sync(~0u, sA, 1); sA += __shfl_xor_sync(~0u, sA, 2);
        dA += __shfl_xor_sync(~0u, dA, 1); dA += __shfl_xor_sync(~0u, dA, 2);
        sB += __shfl_xor_sync(~0u, sB, 1); sB += __shfl_xor_sync(~0u, sB, 2);
        dB += __shfl_xor_sync(~0u, dB, 1); dB += __shfl_xor_sync(~0u, dB, 2);
        if (head == tq) { keep_sA = sA; keep_dA = dA; keep_sB = sB; keep_dB = dB; }
    }
    if (mA < N_NODES) {
        g_asrc[mA * HEADS + tq] = keep_sA;
        g_adst[mA * HEADS + tq] = keep_dA;
#pragma unroll
        for (int nt = 0; nt < 16; ++nt)
            *(float2*)(g_h + (size_t)mA * HC + nt * 8 + 2 * tq) =
                make_float2(c[nt][0], c[nt][1]);
    }
    if (mB < N_NODES) {
        g_asrc[mB * HEADS + tq] = keep_sB;
        g_adst[mB * HEADS + tq] = keep_dB;
#pragma unroll
        for (int nt = 0; nt < 16; ++nt)
            *(float2*)(g_h + (size_t)mB * HC + nt * 8 + 2 * tq) =
                make_float2(c[nt][2], c[nt][3]);
    }
}

// ---------------- aggregation: warp per node, 1 exp per lane per edge -------
__global__ __launch_bounds__(256) void k_agg(const float* __restrict__ bias,
                                             float* __restrict__ out) {
    int w = (blockIdx.x * blockDim.x + threadIdx.x) >> 5;
    int lane = threadIdx.x & 31;
    if (w >= N_NODES) return;
    int s0 = g_off[w], s1 = g_off[w + 1];
    int head = lane >> 3;
    float adm = g_adst[w * HEADS + head];

    float4 acc = make_float4(0.f, 0.f, 0.f, 0.f);
    float den = 0.f;

    int s = g_csr[s0];
    float asv = __ldg(&g_asrc[s * HEADS + head]);
    for (int i = s0; i < s1; ++i) {
        int snext = (i + 1 < s1) ? g_csr[i + 1] : s;
        float asn = __ldg(&g_asrc[snext * HEADS + head]);
        float e = asv + adm;
        e = (e >= 0.f) ? e : 0.2f * e;
        float ph = __expf(e);
        den += ph;
        float4 hv = ((const float4*)(g_h + (size_t)s * HC))[lane];
        acc.x += ph * hv.x; acc.y += ph * hv.y;
        acc.z += ph * hv.z; acc.w += ph * hv.w;
        s = snext; asv = asn;
    }
    float inv = 1.f / (den + 1e-16f);
    float4 b = ((const float4*)bias)[lane];
    float4 o4;
    o4.x = fmaxf(acc.x * inv + b.x, 0.f);
    o4.y = fmaxf(acc.y * inv + b.y, 0.f);
    o4.z = fmaxf(acc.z * inv + b.z, 0.f);
    o4.w = fmaxf(acc.w * inv + b.w, 0.f);
    ((float4*)(out + (size_t)w * HC))[lane] = o4;
}

// ---------------- launch ----------------------------------------------------
extern "C" void kernel_launch(void* const* d_in, const int* in_sizes, int n_in,
                              void* d_out, int out_size) {
    const float* x       = (const float*)d_in[0];
    const void*  ei      = d_in[1];
    const float* W       = (const float*)d_in[2];
    const float* att_src = (const float*)d_in[3];
    const float* att_dst = (const float*)d_in[4];
    const float* bias    = (const float*)d_in[5];
    float*       out     = (float*)d_out;

    (void)in_sizes; (void)n_in; (void)out_size;

    const int TB = 256;
    cudaStream_t s2 = g_sh.s;

    cudaEventRecord(g_sh.eFork, 0);
    cudaStreamWaitEvent(s2, g_sh.eFork, 0);

    k_init<<<(N_NODES + TB - 1) / TB, TB, 0, s2>>>((const int*)ei);
    k_hist<<<(N_EDGES / 4 + TB - 1) / TB, TB, 0, s2>>>(ei);
    k_bsum<<<NBLK, 256, 0, s2>>>();
    k_bscan<<<1, 256, 0, s2>>>();
    k_offsets<<<NBLK, 256, 0, s2>>>();
    k_scatter<<<(N_EDGES / 4 + TB - 1) / TB, TB, 0, s2>>>(ei);
    cudaEventRecord(g_sh.eJoin, s2);

    k_gemm<<<(N_NODES + 127) / 128, 256>>>(x, W, att_src, att_dst);

    cudaStreamWaitEvent(0, g_sh.eJoin, 0);
    k_agg<<<(N_NODES * 32 + TB - 1) / TB, TB>>>(bias, out);
}